// round 4
// baseline (speedup 1.0000x reference)
#include <cuda_runtime.h>

// z_hat [B,T,D] f32, P [B,T] f32, lengths [B] i32 -> out [B,T,D] f32
#define BB 4
#define TT 4096
#define DD 512
#define CC 128          // chunks along T
#define LL 32           // chunk length
#define HALF 16         // rows per thread-half
#define D4 (DD/4)       // float4 lanes (128)
#define PF 8            // combine prefetch depth
#define NBLK (BB*CC)    // 512 (power of 2)

// Scratch (__device__ globals; allocation-free rule)
__device__ float g_Bsum[BB * CC * DD];
__device__ float g_A[BB * CC];
__device__ float g_Zinit[BB * CC * DD];
__device__ unsigned g_ctr;   // monotonically increasing; mod-512 wrap => no reset needed,
                             // behavior identical every launch (output-deterministic)

// ---------------------------------------------------------------------------
// Kernel A: per-chunk summaries + fused cross-chunk combine (last block).
//   Bsum[b,c,d] = sum_k w[k]*x[k,d],  w[k] = p[k]*prod_{j>k} q[j] (full-chunk
//   suffix weights in smem -> the two thread-halves just ADD their partials).
//   A[b,c] = prod_k q[k].
//   Last finishing block computes Zinit for all batches (pipelined; x/y/z/w
//   FMA chains independent -> 4 cyc serial depth per chunk).
// ---------------------------------------------------------------------------
__global__ void __launch_bounds__(256) kA_summary_combine(
    const float* __restrict__ z, const float* __restrict__ P,
    const int* __restrict__ lengths)
{
    const int b = blockIdx.x;          // grid (BB, CC): linear = c*BB + b -> batch-mixed
    const int c = blockIdx.y;
    const int tid = threadIdx.x;
    const int lane = tid & 127;        // float4 lane over D
    const int h = tid >> 7;            // chunk half
    const int len = lengths[b];
    const int t0 = c * LL;

    __shared__ float sp[LL], sq[LL], sw[LL];
    __shared__ float sA;
    __shared__ float4 sacc[D4];
    __shared__ int s_last;

    if (t0 < len) {                    // uniform per block
        if (tid < LL) {
            float p = P[b * TT + t0 + tid];
            p = fminf(fmaxf(p, 0.0f), 1.0f - 1e-6f);
            sq[tid] = 1.0f - p;
            sp[tid] = fmaxf(p, 1e-6f);
        }
        __syncthreads();
        if (tid == 0) {
            float r = 1.0f;
#pragma unroll
            for (int k = LL - 1; k >= 0; --k) { sw[k] = sp[k] * r; r *= sq[k]; }
            sA = r;
        }
        __syncthreads();

        const float4* __restrict__ zp =
            (const float4*)(z + ((size_t)b * TT + t0 + h * HALF) * DD);

        float4 acc = make_float4(0.f, 0.f, 0.f, 0.f);
#pragma unroll
        for (int kb = 0; kb < HALF; kb += 4) {   // batch-4 loads for MLP
            float4 x0 = zp[(size_t)(kb + 0) * D4 + lane];
            float4 x1 = zp[(size_t)(kb + 1) * D4 + lane];
            float4 x2 = zp[(size_t)(kb + 2) * D4 + lane];
            float4 x3 = zp[(size_t)(kb + 3) * D4 + lane];
            float w0 = sw[h * HALF + kb + 0];
            float w1 = sw[h * HALF + kb + 1];
            float w2 = sw[h * HALF + kb + 2];
            float w3 = sw[h * HALF + kb + 3];
            acc.x = fmaf(w0, x0.x, acc.x); acc.y = fmaf(w0, x0.y, acc.y);
            acc.z = fmaf(w0, x0.z, acc.z); acc.w = fmaf(w0, x0.w, acc.w);
            acc.x = fmaf(w1, x1.x, acc.x); acc.y = fmaf(w1, x1.y, acc.y);
            acc.z = fmaf(w1, x1.z, acc.z); acc.w = fmaf(w1, x1.w, acc.w);
            acc.x = fmaf(w2, x2.x, acc.x); acc.y = fmaf(w2, x2.y, acc.y);
            acc.z = fmaf(w2, x2.z, acc.z); acc.w = fmaf(w2, x2.w, acc.w);
            acc.x = fmaf(w3, x3.x, acc.x); acc.y = fmaf(w3, x3.y, acc.y);
            acc.z = fmaf(w3, x3.z, acc.z); acc.w = fmaf(w3, x3.w, acc.w);
        }
        if (h == 0) sacc[lane] = acc;
        __syncthreads();
        if (h == 1) {                  // full-chunk suffix weights -> plain add
            float4 a0 = sacc[lane];
            acc.x += a0.x; acc.y += a0.y; acc.z += a0.z; acc.w += a0.w;
            ((float4*)g_Bsum)[(size_t)(b * CC + c) * D4 + lane] = acc;
            if (lane == 0) g_A[b * CC + c] = sA;
        }
        __threadfence();
    }

    // last-block detection (all NBLK blocks increment once)
    if (tid == 0) {
        unsigned old = atomicAdd(&g_ctr, 1u);
        s_last = ((old & (NBLK - 1)) == (NBLK - 1)) ? 1 : 0;
    }
    __syncthreads();
    if (!s_last) return;
    __threadfence();

    // Cross-chunk combine: half h handles batches {2h, 2h+1}.
    const float4* __restrict__ bs = (const float4*)g_Bsum;
    float4* __restrict__ zi = (float4*)g_Zinit;
#pragma unroll
    for (int bi = 0; bi < 2; ++bi) {
        const int bb = h * 2 + bi;
        const int cmax = (lengths[bb] + LL - 1) / LL;
        if (cmax == 0) continue;

        float4 zv = make_float4(0.f, 0.f, 0.f, 0.f);
        float4 cs[PF];
        float  ca[PF];
#pragma unroll
        for (int j = 0; j < PF; ++j) {
            int idx = min(j, CC - 1);
            cs[j] = bs[(size_t)(bb * CC + idx) * D4 + lane];
            ca[j] = g_A[bb * CC + idx];
        }
        for (int base = 0; base < cmax; base += PF) {
            float4 ns[PF];
            float  na[PF];
#pragma unroll
            for (int j = 0; j < PF; ++j) {           // prefetch (carry-independent)
                int idx = min(base + PF + j, CC - 1);
                ns[j] = bs[(size_t)(bb * CC + idx) * D4 + lane];
                na[j] = g_A[bb * CC + idx];
            }
#pragma unroll
            for (int j = 0; j < PF; ++j) {           // serial part: 1 FMA depth/chunk
                if (base + j < cmax) {
                    zi[(size_t)(bb * CC + base + j) * D4 + lane] = zv;
                    zv.x = fmaf(ca[j], zv.x, cs[j].x);
                    zv.y = fmaf(ca[j], zv.y, cs[j].y);
                    zv.z = fmaf(ca[j], zv.z, cs[j].z);
                    zv.w = fmaf(ca[j], zv.w, cs[j].w);
                }
            }
#pragma unroll
            for (int j = 0; j < PF; ++j) { cs[j] = ns[j]; ca[j] = na[j]; }
        }
    }
}

// ---------------------------------------------------------------------------
// Kernel B: per-chunk local scan seeded with Zinit; mask; write out.
// Two thread-halves: h1 preloads while h0 scans; smem hands the carry over.
// Fully-masked chunks write zeros with no loads.
// ---------------------------------------------------------------------------
__global__ void __launch_bounds__(256) kB_scan_out(
    const float* __restrict__ z, const float* __restrict__ P,
    const int* __restrict__ lengths, float* __restrict__ out)
{
    const int b = blockIdx.x;
    const int c = blockIdx.y;
    const int tid = threadIdx.x;
    const int lane = tid & 127;
    const int h = tid >> 7;
    const int len = lengths[b];
    const int t0 = c * LL;

    float4* __restrict__ op = (float4*)(out + ((size_t)b * TT + t0) * DD);

    if (t0 >= len) {
        float4 zero = make_float4(0.f, 0.f, 0.f, 0.f);
#pragma unroll
        for (int k = 0; k < HALF; ++k)
            op[(size_t)(h * HALF + k) * D4 + lane] = zero;
        return;
    }

    __shared__ float sp[LL], sq[LL];
    __shared__ float4 mid[D4];

    float4 zinit;
    if (h == 0)   // start carry load early (hides latency behind P/smem setup)
        zinit = ((const float4*)g_Zinit)[(size_t)(b * CC + c) * D4 + lane];

    if (tid < LL) {
        float p = P[b * TT + t0 + tid];
        p = fminf(fmaxf(p, 0.0f), 1.0f - 1e-6f);
        sq[tid] = 1.0f - p;
        sp[tid] = fmaxf(p, 1e-6f);
    }
    __syncthreads();

    const float4* __restrict__ zp =
        (const float4*)(z + ((size_t)b * TT + t0 + h * HALF) * DD);

    // h1 preloads its first batch while h0 scans
    float4 pre0, pre1, pre2, pre3;
    if (h == 1) {
        pre0 = zp[(size_t)0 * D4 + lane];
        pre1 = zp[(size_t)1 * D4 + lane];
        pre2 = zp[(size_t)2 * D4 + lane];
        pre3 = zp[(size_t)3 * D4 + lane];
    }

    float4 zv;
    if (h == 0) {
        zv = zinit;
#pragma unroll
        for (int kb = 0; kb < HALF; kb += 4) {
            float4 x0 = zp[(size_t)(kb + 0) * D4 + lane];
            float4 x1 = zp[(size_t)(kb + 1) * D4 + lane];
            float4 x2 = zp[(size_t)(kb + 2) * D4 + lane];
            float4 x3 = zp[(size_t)(kb + 3) * D4 + lane];
#pragma unroll
            for (int j = 0; j < 4; ++j) {
                const int kk = kb + j;
                float4 x = (j == 0) ? x0 : (j == 1) ? x1 : (j == 2) ? x2 : x3;
                float q = sq[kk], p = sp[kk];
                zv.x = fmaf(q, zv.x, p * x.x);
                zv.y = fmaf(q, zv.y, p * x.y);
                zv.z = fmaf(q, zv.z, p * x.z);
                zv.w = fmaf(q, zv.w, p * x.w);
                float m = (t0 + kk < len) ? 1.0f : 0.0f;
                op[(size_t)kk * D4 + lane] =
                    make_float4(zv.x * m, zv.y * m, zv.z * m, zv.w * m);
            }
        }
        mid[lane] = zv;
    }
    __syncthreads();
    if (h == 1) {
        zv = mid[lane];
#pragma unroll
        for (int kb = 0; kb < HALF; kb += 4) {
            float4 x0, x1, x2, x3;
            if (kb == 0) { x0 = pre0; x1 = pre1; x2 = pre2; x3 = pre3; }
            else {
                x0 = zp[(size_t)(kb + 0) * D4 + lane];
                x1 = zp[(size_t)(kb + 1) * D4 + lane];
                x2 = zp[(size_t)(kb + 2) * D4 + lane];
                x3 = zp[(size_t)(kb + 3) * D4 + lane];
            }
#pragma unroll
            for (int j = 0; j < 4; ++j) {
                const int kk = HALF + kb + j;
                float4 x = (j == 0) ? x0 : (j == 1) ? x1 : (j == 2) ? x2 : x3;
                float q = sq[kk], p = sp[kk];
                zv.x = fmaf(q, zv.x, p * x.x);
                zv.y = fmaf(q, zv.y, p * x.y);
                zv.z = fmaf(q, zv.z, p * x.z);
                zv.w = fmaf(q, zv.w, p * x.w);
                float m = (t0 + kk < len) ? 1.0f : 0.0f;
                op[(size_t)kk * D4 + lane] =
                    make_float4(zv.x * m, zv.y * m, zv.z * m, zv.w * m);
            }
        }
    }
}

extern "C" void kernel_launch(void* const* d_in, const int* in_sizes, int n_in,
                              void* d_out, int out_size)
{
    const float* z = (const float*)d_in[0];
    const float* P = (const float*)d_in[1];
    const int* lengths = (const int*)d_in[2];
    float* out = (float*)d_out;

    dim3 grid(BB, CC);   // linear order = c*BB + b -> batch-interleaved scheduling
    kA_summary_combine<<<grid, 256>>>(z, P, lengths);
    kB_scan_out<<<grid, 256>>>(z, P, lengths, out);
}

// round 5
// speedup vs baseline: 1.7966x; 1.7966x over previous
#include <cuda_runtime.h>

// z_hat [B,T,D] f32, P [B,T] f32, lengths [B] i32 -> out [B,T,D] f32
#define BB 4
#define TT 4096
#define DD 512
#define CC 256          // chunks along T (threads in k2 scan)
#define LL 16           // chunk length
#define D4 (DD/4)       // float4 lanes per row (128)

// Scratch (__device__ globals; allocation-free rule)
__device__ float g_Bsum[BB * CC * DD];
__device__ float g_A[BB * CC];
__device__ float g_Zinit[BB * CC * DD];

// ---------------------------------------------------------------------------
// K1: per-chunk weighted reduction (no serial chain).
//   Bsum[b,c,d] = sum_k w[k]*x[k,d], w[k]=p[k]*prod_{j>k}q[j];  A[b,c]=prod q.
// Loads batched 8-deep into registers => MLP=8 per thread.
// ---------------------------------------------------------------------------
__global__ void __launch_bounds__(128) k1_chunk_summary(
    const float* __restrict__ z, const float* __restrict__ P,
    const int* __restrict__ lengths)
{
    const int b = blockIdx.x;     // fastest -> batch-interleaved scheduling
    const int c = blockIdx.y;
    const int lane = threadIdx.x; // float4 lane over D
    const int len = lengths[b];
    const int t0 = c * LL;
    if (t0 >= len) return;        // masked chunk: state never consumed

    __shared__ float sw[LL];
    __shared__ float sp[LL], sq[LL];

    if (lane < LL) {
        float p = P[b * TT + t0 + lane];
        p = fminf(fmaxf(p, 0.0f), 1.0f - 1e-6f);
        sq[lane] = 1.0f - p;
        sp[lane] = fmaxf(p, 1e-6f);
    }
    __syncthreads();
    if (lane == 0) {
        float r = 1.0f;
#pragma unroll
        for (int k = LL - 1; k >= 0; --k) { sw[k] = sp[k] * r; r *= sq[k]; }
        g_A[b * CC + c] = r;
    }
    __syncthreads();

    const float4* __restrict__ zp =
        (const float4*)(z + ((size_t)b * TT + t0) * DD);

    float4 acc = make_float4(0.f, 0.f, 0.f, 0.f);
#pragma unroll
    for (int kb = 0; kb < LL; kb += 8) {
        float4 x0 = zp[(size_t)(kb + 0) * D4 + lane];
        float4 x1 = zp[(size_t)(kb + 1) * D4 + lane];
        float4 x2 = zp[(size_t)(kb + 2) * D4 + lane];
        float4 x3 = zp[(size_t)(kb + 3) * D4 + lane];
        float4 x4 = zp[(size_t)(kb + 4) * D4 + lane];
        float4 x5 = zp[(size_t)(kb + 5) * D4 + lane];
        float4 x6 = zp[(size_t)(kb + 6) * D4 + lane];
        float4 x7 = zp[(size_t)(kb + 7) * D4 + lane];
        float w0 = sw[kb + 0], w1 = sw[kb + 1], w2 = sw[kb + 2], w3 = sw[kb + 3];
        float w4 = sw[kb + 4], w5 = sw[kb + 5], w6 = sw[kb + 6], w7 = sw[kb + 7];
        acc.x = fmaf(w0, x0.x, acc.x); acc.y = fmaf(w0, x0.y, acc.y);
        acc.z = fmaf(w0, x0.z, acc.z); acc.w = fmaf(w0, x0.w, acc.w);
        acc.x = fmaf(w1, x1.x, acc.x); acc.y = fmaf(w1, x1.y, acc.y);
        acc.z = fmaf(w1, x1.z, acc.z); acc.w = fmaf(w1, x1.w, acc.w);
        acc.x = fmaf(w2, x2.x, acc.x); acc.y = fmaf(w2, x2.y, acc.y);
        acc.z = fmaf(w2, x2.z, acc.z); acc.w = fmaf(w2, x2.w, acc.w);
        acc.x = fmaf(w3, x3.x, acc.x); acc.y = fmaf(w3, x3.y, acc.y);
        acc.z = fmaf(w3, x3.z, acc.z); acc.w = fmaf(w3, x3.w, acc.w);
        acc.x = fmaf(w4, x4.x, acc.x); acc.y = fmaf(w4, x4.y, acc.y);
        acc.z = fmaf(w4, x4.z, acc.z); acc.w = fmaf(w4, x4.w, acc.w);
        acc.x = fmaf(w5, x5.x, acc.x); acc.y = fmaf(w5, x5.y, acc.y);
        acc.z = fmaf(w5, x5.z, acc.z); acc.w = fmaf(w5, x5.w, acc.w);
        acc.x = fmaf(w6, x6.x, acc.x); acc.y = fmaf(w6, x6.y, acc.y);
        acc.z = fmaf(w6, x6.z, acc.z); acc.w = fmaf(w6, x6.w, acc.w);
        acc.x = fmaf(w7, x7.x, acc.x); acc.y = fmaf(w7, x7.y, acc.y);
        acc.z = fmaf(w7, x7.z, acc.z); acc.w = fmaf(w7, x7.w, acc.w);
    }
    ((float4*)g_Bsum)[(size_t)(b * CC + c) * D4 + lane] = acc;
}

// ---------------------------------------------------------------------------
// K2: PARALLEL cross-chunk scan (Hillis-Steele over affine maps).
// Block = (b, d4-lane). Thread c owns chunk c's map (A[c], Bsum[c, lane]).
// Inclusive scan with composition (A2,B2)∘(A1,B1) = (A2*A1, A2*B1+B2);
// Zinit[c] = B-part of inclusive scan at c-1 (exclusive), Zinit[0] = 0.
// Depth: log2(CC)=8 smem steps. Garbage in masked chunks (c >= cmax) only
// flows upward (prefix property) -> never touches live Zinit entries.
// ---------------------------------------------------------------------------
__global__ void __launch_bounds__(CC) k2_scan()
{
    const int b = blockIdx.x;     // fastest
    const int g = blockIdx.y;     // d4 lane 0..127
    const int c = threadIdx.x;    // chunk id 0..CC-1

    __shared__ float sA[CC];
    __shared__ float4 sB[CC];

    float a = g_A[b * CC + c];
    float4 v = ((const float4*)g_Bsum)[(size_t)(b * CC + c) * D4 + g];
    sA[c] = a; sB[c] = v;
    __syncthreads();

#pragma unroll
    for (int s = 1; s < CC; s <<= 1) {
        float pa = 1.0f;
        float4 pb = make_float4(0.f, 0.f, 0.f, 0.f);
        if (c >= s) { pa = sA[c - s]; pb = sB[c - s]; }
        __syncthreads();
        if (c >= s) {
            // compose: earlier map (pa,pb) then this map (a,v)
            v.x = fmaf(a, pb.x, v.x);
            v.y = fmaf(a, pb.y, v.y);
            v.z = fmaf(a, pb.z, v.z);
            v.w = fmaf(a, pb.w, v.w);
            a *= pa;
            sA[c] = a; sB[c] = v;
        }
        __syncthreads();
    }

    // exclusive: Zinit[c] = inclusiveB[c-1]; Zinit[0] = 0
    float4 zo = (c == 0) ? make_float4(0.f, 0.f, 0.f, 0.f) : sB[c - 1];
    ((float4*)g_Zinit)[(size_t)(b * CC + c) * D4 + g] = zo;
}

// ---------------------------------------------------------------------------
// K3: per-chunk local scan seeded with Zinit; mask; write out.
// Loads batched 8-deep; serial chain is LL FMAs (x/y/z/w independent).
// Fully-masked chunks write zeros with no loads.
// ---------------------------------------------------------------------------
__global__ void __launch_bounds__(128) k3_scan_out(
    const float* __restrict__ z, const float* __restrict__ P,
    const int* __restrict__ lengths, float* __restrict__ out)
{
    const int b = blockIdx.x;
    const int c = blockIdx.y;
    const int lane = threadIdx.x;
    const int len = lengths[b];
    const int t0 = c * LL;

    float4* __restrict__ op = (float4*)(out + ((size_t)b * TT + t0) * DD);

    if (t0 >= len) {
        float4 zero = make_float4(0.f, 0.f, 0.f, 0.f);
#pragma unroll
        for (int k = 0; k < LL; ++k) op[(size_t)k * D4 + lane] = zero;
        return;
    }

    __shared__ float sp[LL], sq[LL];

    // carry load issued early, latency hidden behind P/smem setup
    float4 zv = ((const float4*)g_Zinit)[(size_t)(b * CC + c) * D4 + lane];

    if (lane < LL) {
        float p = P[b * TT + t0 + lane];
        p = fminf(fmaxf(p, 0.0f), 1.0f - 1e-6f);
        sq[lane] = 1.0f - p;
        sp[lane] = fmaxf(p, 1e-6f);
    }
    __syncthreads();

    const float4* __restrict__ zp =
        (const float4*)(z + ((size_t)b * TT + t0) * DD);

#pragma unroll
    for (int kb = 0; kb < LL; kb += 8) {
        float4 x0 = zp[(size_t)(kb + 0) * D4 + lane];
        float4 x1 = zp[(size_t)(kb + 1) * D4 + lane];
        float4 x2 = zp[(size_t)(kb + 2) * D4 + lane];
        float4 x3 = zp[(size_t)(kb + 3) * D4 + lane];
        float4 x4 = zp[(size_t)(kb + 4) * D4 + lane];
        float4 x5 = zp[(size_t)(kb + 5) * D4 + lane];
        float4 x6 = zp[(size_t)(kb + 6) * D4 + lane];
        float4 x7 = zp[(size_t)(kb + 7) * D4 + lane];
#pragma unroll
        for (int j = 0; j < 8; ++j) {
            const int kk = kb + j;
            float4 x = (j == 0) ? x0 : (j == 1) ? x1 : (j == 2) ? x2 : (j == 3) ? x3
                     : (j == 4) ? x4 : (j == 5) ? x5 : (j == 6) ? x6 : x7;
            float q = sq[kk], p = sp[kk];
            zv.x = fmaf(q, zv.x, p * x.x);
            zv.y = fmaf(q, zv.y, p * x.y);
            zv.z = fmaf(q, zv.z, p * x.z);
            zv.w = fmaf(q, zv.w, p * x.w);
            float m = (t0 + kk < len) ? 1.0f : 0.0f;
            op[(size_t)kk * D4 + lane] =
                make_float4(zv.x * m, zv.y * m, zv.z * m, zv.w * m);
        }
    }
}

extern "C" void kernel_launch(void* const* d_in, const int* in_sizes, int n_in,
                              void* d_out, int out_size)
{
    const float* z = (const float*)d_in[0];
    const float* P = (const float*)d_in[1];
    const int* lengths = (const int*)d_in[2];
    float* out = (float*)d_out;

    dim3 gridA(BB, CC);        // b fastest -> masked/active blocks mixed across SMs
    k1_chunk_summary<<<gridA, 128>>>(z, P, lengths);
    dim3 gridS(BB, D4);
    k2_scan<<<gridS, CC>>>();
    k3_scan_out<<<gridA, 128>>>(z, P, lengths, out);
}